// round 17
// baseline (speedup 1.0000x reference)
#include <cuda_runtime.h>
#include <cuda_fp16.h>
#include <cstdint>

// ---------------------------------------------------------------------------
// Problem constants
// ---------------------------------------------------------------------------
#define DD    101                 // inner dim
#define KO    101                 // output cols
#define KPAD2 112                 // 7 * 16 (fp16 k16 steps)
#define BM    64                  // batch rows per tile
#define NGRP  4                   // compute groups (4 warps each)
#define NSLOT 7                   // ring slots
#define NTHR  (NGRP * 128 + 32)   // 544

// B image (fp16): [kt][n][tg] -> two words:
//   w0 = half2( A[k0+2tg][n],   A[k0+2tg+1][n] )
//   w1 = half2( A[k0+2tg+8][n], A[k0+2tg+9][n] ),  k0 = kt*16
#define A_IMG_BYTES (7 * 104 * 4 * 8)     // 23296

#define TILE_BYTES (BM * DD * 4)          // 25856 (slot size, exact)

// smem layout (bytes): [A][7 slots][256 zero pad][mbars]
#define AIMG_OFF 0
#define RAWBASE  A_IMG_BYTES                       // 23296
#define PAD_OFF  (RAWBASE + NSLOT * TILE_BYTES)    // 204288
#define MBAR_OFF (PAD_OFF + 256)                   // 204544
#define SMEM_BYTES 204672

#define GRID 148                          // 1 CTA/SM; CTA b owns tiles b+148c

__device__ __align__(16) unsigned char g_Apair[A_IMG_BYTES];

// ---------------------------------------------------------------------------
// Helpers
// ---------------------------------------------------------------------------
__device__ __forceinline__ uint32_t smem_u32(const void* p) {
    uint32_t a;
    asm("{ .reg .u64 t; cvta.to.shared.u64 t, %1; cvt.u32.u64 %0, t; }"
        : "=r"(a) : "l"(p));
    return a;
}
__device__ __forceinline__ void mbar_init(uint32_t m, uint32_t cnt) {
    asm volatile("mbarrier.init.shared.b64 [%0], %1;" :: "r"(m), "r"(cnt) : "memory");
}
__device__ __forceinline__ void mbar_arrive(uint32_t m) {
    asm volatile("mbarrier.arrive.shared.b64 _, [%0];" :: "r"(m) : "memory");
}
__device__ __forceinline__ void mbar_expect_tx(uint32_t m, uint32_t bytes) {
    asm volatile("mbarrier.arrive.expect_tx.shared.b64 _, [%0], %1;"
                 :: "r"(m), "r"(bytes) : "memory");
}
__device__ __forceinline__ void mbar_wait(uint32_t m, uint32_t parity) {
    asm volatile(
        "{\n\t.reg .pred P;\n"
        "W_%=:\n\t"
        "mbarrier.try_wait.parity.acquire.cta.shared::cta.b64 P, [%0], %1;\n\t"
        "@!P bra W_%=;\n\t}"
        :: "r"(m), "r"(parity) : "memory");
}
__device__ __forceinline__ void bulk_g2s(uint32_t dst, const void* src,
                                         uint32_t bytes, uint32_t m) {
    asm volatile(
        "cp.async.bulk.shared::cta.global.mbarrier::complete_tx::bytes "
        "[%0], [%1], %2, [%3];"
        :: "r"(dst), "l"(src), "r"(bytes), "r"(m) : "memory");
}
__device__ __forceinline__ void bulk_s2g(void* gdst, uint32_t ssrc, uint32_t bytes) {
    asm volatile("cp.async.bulk.global.shared::cta.bulk_group [%0], [%1], %2;"
                 :: "l"(gdst), "r"(ssrc), "r"(bytes) : "memory");
}
#define S2G_COMMIT() asm volatile("cp.async.bulk.commit_group;" ::: "memory")
#define S2G_WAIT0()  asm volatile("cp.async.bulk.wait_group 0;" ::: "memory")
#define GRP_BAR(id)  asm volatile("bar.sync %0, 128;" :: "r"(id) : "memory")
#define FENCE_ASYNC() asm volatile("fence.proxy.async.shared::cta;" ::: "memory")

__device__ __forceinline__ float ldsf(uint32_t a) {
    float v;
    asm volatile("ld.shared.f32 %0, [%1];" : "=f"(v) : "r"(a));
    return v;
}
__device__ __forceinline__ float2 ldsv2f(uint32_t a) {   // 8B-aligned only
    float2 v;
    asm volatile("ld.shared.v2.f32 {%0,%1}, [%2];" : "=f"(v.x), "=f"(v.y) : "r"(a));
    return v;
}
__device__ __forceinline__ void ldsv2(uint32_t* r, uint32_t a) {
    asm volatile("ld.shared.v2.b32 {%0,%1}, [%2];"
                 : "=r"(r[0]), "=r"(r[1]) : "r"(a));
}
__device__ __forceinline__ void stsf(uint32_t a, float v) {
    asm volatile("st.shared.f32 [%0], %1;" :: "r"(a), "f"(v) : "memory");
}
__device__ __forceinline__ void stsv2(uint32_t a, float v0, float v1) {  // 8B-aligned
    asm volatile("st.shared.v2.f32 [%0], {%1,%2};"
                 :: "r"(a), "f"(v0), "f"(v1) : "memory");
}
// pack two f32 -> f16x2 word (PTX cvt d = {hi, lo}; lo is FIRST logical k)
__device__ __forceinline__ uint32_t pack_h2(float lo, float hi) {
    uint32_t r;
    asm("cvt.rn.f16x2.f32 %0, %1, %2;" : "=r"(r) : "f"(hi), "f"(lo));
    return r;
}
__device__ __forceinline__ void mma_f16(float* c, const uint32_t* a,
                                        const uint32_t* b) {
    asm volatile(
        "mma.sync.aligned.m16n8k16.row.col.f32.f16.f16.f32 "
        "{%0,%1,%2,%3}, {%4,%5,%6,%7}, {%8,%9}, {%0,%1,%2,%3};"
        : "+f"(c[0]), "+f"(c[1]), "+f"(c[2]), "+f"(c[3])
        : "r"(a[0]), "r"(a[1]), "r"(a[2]), "r"(a[3]), "r"(b[0]), "r"(b[1]));
}

// ---------------------------------------------------------------------------
// Kernel 1 (closed form): ReJ/ImJ are sparse selections, so
//   A[n,d] = ( Wre[n,d] + [d>=1]*Wre[n,101-d] ) / 101          d <= 50
//   A[n,d] = ( Wim[n,151-d] - Wim[n,d-50] ) / 101              51 <= d <= 100
// stored fp16 into the k16 frag-pair image.
// ---------------------------------------------------------------------------
__global__ void build_A_kernel(const float* __restrict__ Wre,
                               const float* __restrict__ Wim) {
    const int n = blockIdx.x;       // 0..103
    const int d = threadIdx.x;      // 0..111
    float a = 0.0f;
    if (n < KO && d < DD) {
        if (d <= 50) {
            a = Wre[n * DD + d];
            if (d >= 1) a += Wre[n * DD + (101 - d)];
        } else {
            a = Wim[n * DD + (151 - d)] - Wim[n * DD + (d - 50)];
        }
        a *= (1.0f / 101.0f);
    }
    const int kt   = d >> 4;        // 0..6
    const int r    = d & 15;
    const int slot = r >> 3;        // 0: k0+2tg{+1}, 1: k0+2tg+8{+1}
    const int rr   = r & 7;
    const int tg   = rr >> 1;
    const int o    = rr & 1;        // lo/hi half of the word
    const uint32_t addr = (uint32_t)(((kt * 104 + n) * 4 + tg) * 8
                                     + slot * 4 + o * 2);
    *(__half*)(g_Apair + addr) = __float2half(a);
}

// ---------------------------------------------------------------------------
// Kernel 2: ring-buffer persistent GEMM, fp16 m16n8k16 single-pass.
// Parity-split physical row permutation (warp mwarp m, lane group g):
//   f=0 (EVEN rows):  lo = 32m + 8(g&3) + 2(g>>2),  hi = lo + 4
//   f=1 (ODD rows):   lo,hi = f0 rows + 1
// f0 a-frags use conflict-free 8B-aligned ld.shared.v2.f32; f1 uses scalars
// (2-way, forced by fixed parity). Epilogue mirrors: v2 stores for f0.
// ---------------------------------------------------------------------------
extern __shared__ unsigned char smem[];

__global__ void __launch_bounds__(NTHR, 1)
fourier_mma_kernel(const float* __restrict__ x, float* __restrict__ out,
                   int ntiles) {
    const int tid   = threadIdx.x;
    const int wid   = tid >> 5;       // 0..16
    const int grp   = tid >> 7;       // 0..3 consumers, 4 producer
    const int gtid  = tid & 127;
    const int w4    = (tid >> 5) & 3;
    const int lane  = tid & 31;
    const int g     = lane >> 2;
    const int tg    = lane & 3;
    const int mwarp = w4 >> 1;
    const int nhalf = w4 & 1;
    const int NT    = nhalf ? 6 : 7;
    const uint32_t sbase = smem_u32(smem);
    const uint32_t mbF = sbase + MBAR_OFF;        // full[7]
    const uint32_t mbE = sbase + MBAR_OFF + 56;   // empty[7]
    const uint32_t mbA = sbase + MBAR_OFF + 112;

    const int climit = (ntiles - (int)blockIdx.x + GRID - 1) / GRID;

    // zero-fill all slots + pad (finite data everywhere before first MMA)
    for (int i = tid; i < (NSLOT * TILE_BYTES + 256) / 4; i += NTHR)
        *(uint32_t*)(smem + RAWBASE + i * 4) = 0;
    if (tid == 0) {
        #pragma unroll
        for (int i = 0; i < NSLOT; ++i) {
            mbar_init(mbF + i * 8, 1);
            mbar_init(mbE + i * 8, 1);
        }
        mbar_init(mbA, 1);
        mbar_expect_tx(mbA, A_IMG_BYTES);
        bulk_g2s(sbase + AIMG_OFF, g_Apair, A_IMG_BYTES, mbA);
    }
    __syncthreads();

    // ---- producer warp ----
    if (wid == 16) {
        if (lane == 0) {
            FENCE_ASYNC();
            const char* xb = (const char*)x + (size_t)blockIdx.x * TILE_BYTES;
            #pragma unroll 1
            for (int c = 0; c < climit; ++c) {
                const int s = c % NSLOT;
                const int k = c / NSLOT;
                if (k > 0) mbar_wait(mbE + s * 8, (uint32_t)((k - 1) & 1));
                mbar_expect_tx(mbF + s * 8, TILE_BYTES);
                bulk_g2s(sbase + RAWBASE + (uint32_t)s * TILE_BYTES,
                         xb + (size_t)c * (GRID * TILE_BYTES),
                         TILE_BYTES, mbF + s * 8);
            }
        }
        return;
    }

    // ---- consumers ----
    mbar_wait(mbA, 0);

    // physical rows: f0 lo even, f1 lo = +1 (odd); hi = lo + 4
    const int r0e = 32 * mwarp + 8 * (g & 3) + 2 * (g >> 2);   // even
    const uint32_t ra0 = (uint32_t)(r0e * DD + 2 * tg) * 4u;         // f0 (8B-aligned)
    const uint32_t ra1 = (uint32_t)((r0e + 1) * DD + 2 * tg) * 4u;   // f1 (odd row)
    // b pair base: [kt=0][n = nhalf*56 + g][tg] (8B entries)
    const uint32_t rbA = sbase + AIMG_OFF
        + (uint32_t)(((nhalf * 56 + g) * 4 + tg) * 8);
    const int barid = grp + 1;

    #pragma unroll 1
    for (int c = grp; c < climit; c += NGRP) {
        const int s = c % NSLOT;
        const int k = c / NSLOT;
        mbar_wait(mbF + s * 8, (uint32_t)(k & 1));

        float acc[2][7][4];
        #pragma unroll
        for (int f = 0; f < 2; ++f)
            #pragma unroll
            for (int nt = 0; nt < 7; ++nt)
                #pragma unroll
                for (int i = 0; i < 4; ++i) acc[f][nt][i] = 0.0f;

        const uint32_t rawb = sbase + RAWBASE + (uint32_t)s * TILE_BYTES;
        const uint32_t rx0 = rawb + ra0;
        const uint32_t rx1 = rawb + ra1;

        #pragma unroll
        for (int kt = 0; kt < 7; ++kt) {
            const uint32_t ko = (uint32_t)kt * 64u;   // 16 k-words
            uint32_t a0[4], a1[4];
            {   // f=0 (even rows): aligned, conflict-free v2
                const uint32_t p = rx0 + ko;
                float2 v0 = ldsv2f(p);            // row lo,   k 2tg..
                float2 v1 = ldsv2f(p + 1616);     // row lo+4  (4*101*4)
                float2 v2 = ldsv2f(p + 32);       // row lo,   k+8
                float2 v3 = ldsv2f(p + 1648);     // row lo+4, k+8
                a0[0] = pack_h2(v0.x, v0.y);
                a0[1] = pack_h2(v1.x, v1.y);
                a0[2] = pack_h2(v2.x, v2.y);
                a0[3] = pack_h2(v3.x, v3.y);
            }
            {   // f=1 (odd rows): scalar (v2 would be misaligned)
                const uint32_t p = rx1 + ko;
                a1[0] = pack_h2(ldsf(p),          ldsf(p + 4));
                a1[1] = pack_h2(ldsf(p + 1616),   ldsf(p + 1620));
                a1[2] = pack_h2(ldsf(p + 32),     ldsf(p + 36));
                a1[3] = pack_h2(ldsf(p + 1648),   ldsf(p + 1652));
            }

            const uint32_t kb = rbA + (uint32_t)kt * 3328u;   // 104*4*8
            uint32_t b[7][2];
            #pragma unroll
            for (int nt = 0; nt < 7; ++nt)
                if (nt < NT) ldsv2(b[nt], kb + (uint32_t)nt * 256u);

            #pragma unroll
            for (int nt = 0; nt < 7; ++nt)
                if (nt < NT) mma_f16(acc[0][nt], a0, b[nt]);
            #pragma unroll
            for (int nt = 0; nt < 7; ++nt)
                if (nt < NT) mma_f16(acc[1][nt], a1, b[nt]);
        }

        // ---- epilogue: stage [64 x 101] fp32 image back into the slot ----
        GRP_BAR(barid);
        {
            // f=0: even rows -> aligned v2 stores
            const uint32_t se0 = rawb + (uint32_t)(r0e * KO) * 4u;        // row lo
            const uint32_t se1 = se0 + (uint32_t)(4 * KO) * 4u;           // row lo+4
            // f=1: odd rows -> scalar stores
            const uint32_t so0 = rawb + (uint32_t)((r0e + 1) * KO) * 4u;
            const uint32_t so1 = so0 + (uint32_t)(4 * KO) * 4u;
            #pragma unroll
            for (int nt = 0; nt < 7; ++nt) {
                if (nt >= NT) break;
                const int col = nhalf * 56 + nt * 8 + tg * 2;
                const uint32_t co = (uint32_t)col * 4u;
                if (col + 1 < KO) {
                    stsv2(se0 + co, acc[0][nt][0], acc[0][nt][1]);
                    stsv2(se1 + co, acc[0][nt][2], acc[0][nt][3]);
                    stsf(so0 + co,     acc[1][nt][0]);
                    stsf(so0 + co + 4, acc[1][nt][1]);
                    stsf(so1 + co,     acc[1][nt][2]);
                    stsf(so1 + co + 4, acc[1][nt][3]);
                } else if (col < KO) {
                    stsf(se0 + co, acc[0][nt][0]);
                    stsf(se1 + co, acc[0][nt][2]);
                    stsf(so0 + co, acc[1][nt][0]);
                    stsf(so1 + co, acc[1][nt][2]);
                }
            }
        }
        GRP_BAR(barid);
        if (gtid == 0) {
            const int t = (int)blockIdx.x + GRID * c;
            FENCE_ASYNC();
            bulk_s2g(out + (size_t)t * (BM * KO), rawb, TILE_BYTES);
            S2G_COMMIT();
            S2G_WAIT0();
            mbar_arrive(mbE + s * 8);
        }
    }
}

// ---------------------------------------------------------------------------
// Launch
// ---------------------------------------------------------------------------
extern "C" void kernel_launch(void* const* d_in, const int* in_sizes, int n_in,
                              void* d_out, int out_size) {
    const float* x   = (const float*)d_in[0];
    const float* Wre = (const float*)d_in[1];
    const float* Wim = (const float*)d_in[2];
    float* out = (float*)d_out;

    const int B = in_sizes[0] / DD;       // 262144
    const int ntiles = B / BM;            // 4096

    build_A_kernel<<<104, KPAD2>>>(Wre, Wim);

    cudaFuncSetAttribute(fourier_mma_kernel,
                         cudaFuncAttributeMaxDynamicSharedMemorySize, SMEM_BYTES);
    fourier_mma_kernel<<<GRID, NTHR, SMEM_BYTES>>>(x, out, ntiles);
    (void)n_in; (void)out_size;
}